// round 7
// baseline (speedup 1.0000x reference)
#include <cuda_runtime.h>
#include <cuda_bf16.h>

// Problem dims (fixed by dataset)
#define BB 4
#define TT_ 512
#define UU 128
#define DD 512
#define VV 512
#define MS (BB * TT_)   // 2048 speech rows
#define MT (BB * UU)    // 512 text rows

// Scratch: projected speech / text (both L2-resident)
__device__ float g_sp[MS * VV];   // speech @ W^T          (4 MB)
__device__ float g_tp[MT * VV];   // text @ W^T + bias     (1 MB)

typedef unsigned long long ull;

// Packed fp32x2 helpers (sm_103a)
#define PACK2(d, s) \
    asm("mov.b64 %0, {%1, %1};" : "=l"(d) : "r"(__float_as_uint(s)))
#define FMA2(acc, a, b) \
    asm("fma.rn.f32x2 %0, %1, %2, %0;" : "+l"(acc) : "l"(a), "l"(b))
#define ADD2(acc, b) \
    asm("add.rn.f32x2 %0, %0, %1;" : "+l"(acc) : "l"(b))

// ---------------------------------------------------------------------------
// Kernel 1: joint GEMM.  C[m, v] = sum_d A[m, d] * W[v, d]  (+bias for text)
// 64x64 tiles, BK=16, 128 threads, grid 320 (tiles 0..255 speech, 256..319 text).
// A is stored DUPLICATED in smem ({a,a} pairs) so the FFMA2 broadcast operand
// comes straight from LDS.128 — no movs in the inner loop.
// Micro-tile per thread: 4m x 8v = 16 FFMA2 per kk vs 4 LDS.128.
// ---------------------------------------------------------------------------
__global__ __launch_bounds__(128)
void joint_gemm_kernel(const float* __restrict__ speech,
                       const float* __restrict__ text,
                       const float* __restrict__ Wm,
                       const float* __restrict__ bias,
                       const int* __restrict__ slen,
                       const int* __restrict__ tlen,
                       float* __restrict__ out)
{
    __shared__ __align__(16) float Ad[16][136];  // A duplicated: [k][2m..2m+1]
    __shared__ __align__(16) float Ws[16][72];   // W: [k][n]

    const int t   = blockIdx.x;
    const int tid = threadIdx.x;
    const bool is_text = (t >= 256);
    const int mblk = is_text ? ((t - 256) >> 3) : (t >> 3);
    const int v0   = (t & 7) * 64;

    const float* A = is_text ? text + (size_t)mblk * 64 * DD
                             : speech + (size_t)mblk * 64 * DD;
    float* C = is_text ? g_tp + (size_t)mblk * 64 * VV
                       : g_sp + (size_t)mblk * 64 * VV;

    // loaders: row lr (0..63), k-half lh (0/1 -> k offset 0/8)
    const int lr = tid >> 1;
    const int lh = tid & 1;
    // compute: cols tx*8..+7, rows ty*4..+3
    const int tx = tid & 7;
    const int ty = tid >> 3;

    ull acc[4][4];
#pragma unroll
    for (int i = 0; i < 4; i++)
#pragma unroll
        for (int j = 0; j < 4; j++) acc[i][j] = 0ull;

    const float* Ap = A  + (size_t)lr * DD + lh * 8;
    const float* Wp = Wm + (size_t)(v0 + lr) * DD + lh * 8;

    float4 a0 = *(const float4*)Ap;
    float4 a1 = *(const float4*)(Ap + 4);
    float4 w0 = *(const float4*)Wp;
    float4 w1 = *(const float4*)(Wp + 4);

    for (int k0 = 0; k0 < DD; k0 += 16) {
        __syncthreads();
        {
            float av[8] = {a0.x, a0.y, a0.z, a0.w, a1.x, a1.y, a1.z, a1.w};
            float wv[8] = {w0.x, w0.y, w0.z, w0.w, w1.x, w1.y, w1.z, w1.w};
#pragma unroll
            for (int j = 0; j < 8; j++) {
                ull d;
                PACK2(d, av[j]);
                *(ull*)&Ad[lh * 8 + j][2 * lr] = d;   // {a,a} pair
                Ws[lh * 8 + j][lr] = wv[j];
            }
        }
        __syncthreads();

        if (k0 + 16 < DD) {
            a0 = *(const float4*)(Ap + k0 + 16);
            a1 = *(const float4*)(Ap + k0 + 20);
            w0 = *(const float4*)(Wp + k0 + 16);
            w1 = *(const float4*)(Wp + k0 + 20);
        }

#pragma unroll
        for (int kk = 0; kk < 16; kk++) {
            ulonglong2 wA = *(const ulonglong2*)&Ws[kk][tx * 8];      // cols n..n+3
            ulonglong2 wB = *(const ulonglong2*)&Ws[kk][tx * 8 + 4];  // cols n+4..n+7
            ulonglong2 aA = *(const ulonglong2*)&Ad[kk][ty * 8];      // rows m, m+1 (dup)
            ulonglong2 aB = *(const ulonglong2*)&Ad[kk][ty * 8 + 4];  // rows m+2, m+3

            FMA2(acc[0][0], aA.x, wA.x); FMA2(acc[0][1], aA.x, wA.y);
            FMA2(acc[0][2], aA.x, wB.x); FMA2(acc[0][3], aA.x, wB.y);
            FMA2(acc[1][0], aA.y, wA.x); FMA2(acc[1][1], aA.y, wA.y);
            FMA2(acc[1][2], aA.y, wB.x); FMA2(acc[1][3], aA.y, wB.y);
            FMA2(acc[2][0], aB.x, wA.x); FMA2(acc[2][1], aB.x, wA.y);
            FMA2(acc[2][2], aB.x, wB.x); FMA2(acc[2][3], aB.x, wB.y);
            FMA2(acc[3][0], aB.y, wA.x); FMA2(acc[3][1], aB.y, wA.y);
            FMA2(acc[3][2], aB.y, wB.x); FMA2(acc[3][3], aB.y, wB.y);
        }
    }

    if (is_text) {
        ull b0 = *(const ull*)(bias + v0 + tx * 8);
        ull b1 = *(const ull*)(bias + v0 + tx * 8 + 2);
        ull b2 = *(const ull*)(bias + v0 + tx * 8 + 4);
        ull b3 = *(const ull*)(bias + v0 + tx * 8 + 6);
#pragma unroll
        for (int i = 0; i < 4; i++) {
            ADD2(acc[i][0], b0); ADD2(acc[i][1], b1);
            ADD2(acc[i][2], b2); ADD2(acc[i][3], b3);
        }
    }

#pragma unroll
    for (int i = 0; i < 4; i++) {
        float* cp = C + (size_t)(ty * 4 + i) * VV + v0 + tx * 8;
        ulonglong2 o01, o23;
        o01.x = acc[i][0]; o01.y = acc[i][1];
        o23.x = acc[i][2]; o23.y = acc[i][3];
        *(ulonglong2*)cp       = o01;
        *(ulonglong2*)(cp + 4) = o23;
    }

    // Length tail: outputs 1 and 2 flattened after logits, as float32.
    if (t == 0 && tid < 8) {
        size_t base = (size_t)BB * TT_ * UU * VV;
        if (tid < 4) out[base + tid] = (float)slen[tid];
        else         out[base + tid] = (float)tlen[tid - 4];
    }
}

// ---------------------------------------------------------------------------
// Kernel 2: broadcast add: out[bt, u, v] = sp[bt, v] + tp[b*U + u, v].
// One block per (b,t) row; 128 threads. Proven 87.7 us (HBM write floor).
// ---------------------------------------------------------------------------
__global__ __launch_bounds__(128)
void bcast_add_kernel(float* __restrict__ out)
{
    const int bt  = blockIdx.x;           // 0..2047
    const int b   = bt >> 9;              // bt / T
    const int tid = threadIdx.x;          // 0..127 -> v4 index

    const float4* sp4 = (const float4*)g_sp;
    const float4* tp4 = (const float4*)g_tp;

    float4 s = sp4[(size_t)bt * 128 + tid];

    const float4* tprow = tp4 + (size_t)b * UU * 128 + tid;
    float4* ob = (float4*)out + (size_t)bt * UU * 128 + tid;

#pragma unroll 4
    for (int u = 0; u < UU; u++) {
        float4 t = tprow[(size_t)u * 128];
        float4 r;
        r.x = s.x + t.x;
        r.y = s.y + t.y;
        r.z = s.z + t.z;
        r.w = s.w + t.w;
        ob[(size_t)u * 128] = r;
    }
}

extern "C" void kernel_launch(void* const* d_in, const int* in_sizes, int n_in,
                              void* d_out, int out_size)
{
    const float* speech = (const float*)d_in[0];
    const float* text   = (const float*)d_in[1];
    const float* Wm     = (const float*)d_in[2];
    const float* bias   = (const float*)d_in[3];
    const int*   slen   = (const int*)d_in[4];
    const int*   tlen   = (const int*)d_in[5];

    // Phase 1: both projections (speech + text w/ bias) + length tail
    joint_gemm_kernel<<<320, 128>>>(speech, text, Wm, bias,
                                    slen, tlen, (float*)d_out);

    // Phase 2: broadcast add (DRAM-write-bound floor)
    bcast_add_kernel<<<MS, 128>>>((float*)d_out);
}